// round 13
// baseline (speedup 1.0000x reference)
#include <cuda_runtime.h>
#include <math.h>

#define N_ANCHORS 196416
#define N_CLASSES 90
#define SCORE_THR 0.05f
#define NMS_THR   0.5f
#define MAX_DET   100
#define NBINS     2048
#define KTARGET   384
#define MCAP      512
#define MASK_W    (MCAP / 32)     // 16 words per mask row

#define SCORE_GRID 1184
#define SCORE_BLK  256

// ---- scratch (static device globals; zero-initialized at load) ----
__device__ float          g_scores[N_ANCHORS];
__device__ unsigned char  g_classes[N_ANCHORS];
__device__ unsigned int   g_hist[NBINS];
__device__ int            g_done;      // last-block ticket (self-resetting)
__device__ int            g_cutbin;
__device__ int            g_cand_cnt;  // reset by k_tail
__device__ unsigned long long g_cand[MCAP];   // (score_bits<<32)|~anchor
__device__ float4         g_cbox[MCAP];
__device__ unsigned int   g_mask[MCAP * MASK_W];

__device__ __forceinline__ int score_bin(float s) {
    float d = 1.0f - s;
    if (d < 0.0f) d = 0.0f;
    return (int)(__float_as_uint(d) >> 19);
}

__device__ __forceinline__ unsigned smem_u32(const void* p) {
    return (unsigned)__cvta_generic_to_shared(p);
}

// Warp handles FOUR anchors per iteration (proven-neutral but keeps MLP high).
// Last block scans bins -> g_cutbin.
__global__ void k_score(const float* __restrict__ cls) {
    __shared__ unsigned int shist[NBINS];
    for (int i = threadIdx.x; i < NBINS; i += blockDim.x) shist[i] = 0u;
    __syncthreads();

    const int lane = threadIdx.x & 31;
    const int gw   = blockIdx.x * (SCORE_BLK >> 5) + (threadIdx.x >> 5);
    const int nw   = SCORE_GRID * (SCORE_BLK >> 5);
    const bool has3 = (lane < 26);

    for (int a = 4 * gw; a < N_ANCHORS; a += 4 * nw) {
        const float* r0 = cls + (size_t)a * N_CLASSES;
        const float* r1 = r0 + N_CLASSES;
        const float* r2 = r1 + N_CLASSES;
        const float* r3 = r2 + N_CLASSES;
        float a0 = r0[lane], a1 = r0[lane + 32], a2 = has3 ? r0[lane + 64] : -1.0f;
        float b0 = r1[lane], b1 = r1[lane + 32], b2 = has3 ? r1[lane + 64] : -1.0f;
        float c0 = r2[lane], c1 = r2[lane + 32], c2 = has3 ? r2[lane + 64] : -1.0f;
        float d0 = r3[lane], d1 = r3[lane + 32], d2 = has3 ? r3[lane + 64] : -1.0f;

        float sA = a0; int cA = lane;
        if (a1 > sA) { sA = a1; cA = lane + 32; }
        if (a2 > sA) { sA = a2; cA = lane + 64; }
        float sB = b0; int cB = lane;
        if (b1 > sB) { sB = b1; cB = lane + 32; }
        if (b2 > sB) { sB = b2; cB = lane + 64; }
        float sC = c0; int cC = lane;
        if (c1 > sC) { sC = c1; cC = lane + 32; }
        if (c2 > sC) { sC = c2; cC = lane + 64; }
        float sD = d0; int cD = lane;
        if (d1 > sD) { sD = d1; cD = lane + 32; }
        if (d2 > sD) { sD = d2; cD = lane + 64; }

        unsigned mbA = __reduce_max_sync(0xffffffffu, __float_as_uint(sA));
        unsigned mbB = __reduce_max_sync(0xffffffffu, __float_as_uint(sB));
        unsigned mbC = __reduce_max_sync(0xffffffffu, __float_as_uint(sC));
        unsigned mbD = __reduce_max_sync(0xffffffffu, __float_as_uint(sD));
        unsigned mcA = __reduce_min_sync(0xffffffffu,
                         (__float_as_uint(sA) == mbA) ? (unsigned)cA : 0xFFu);
        unsigned mcB = __reduce_min_sync(0xffffffffu,
                         (__float_as_uint(sB) == mbB) ? (unsigned)cB : 0xFFu);
        unsigned mcC = __reduce_min_sync(0xffffffffu,
                         (__float_as_uint(sC) == mbC) ? (unsigned)cC : 0xFFu);
        unsigned mcD = __reduce_min_sync(0xffffffffu,
                         (__float_as_uint(sD) == mbD) ? (unsigned)cD : 0xFFu);
        if (lane == 0) {
            float msA = __uint_as_float(mbA);
            float msB = __uint_as_float(mbB);
            float msC = __uint_as_float(mbC);
            float msD = __uint_as_float(mbD);
            g_scores[a]      = msA;  g_classes[a]     = (unsigned char)mcA;
            g_scores[a + 1]  = msB;  g_classes[a + 1] = (unsigned char)mcB;
            g_scores[a + 2]  = msC;  g_classes[a + 2] = (unsigned char)mcC;
            g_scores[a + 3]  = msD;  g_classes[a + 3] = (unsigned char)mcD;
            if (msA > SCORE_THR) atomicAdd(&shist[score_bin(msA)], 1u);
            if (msB > SCORE_THR) atomicAdd(&shist[score_bin(msB)], 1u);
            if (msC > SCORE_THR) atomicAdd(&shist[score_bin(msC)], 1u);
            if (msD > SCORE_THR) atomicAdd(&shist[score_bin(msD)], 1u);
        }
    }
    __syncthreads();
    for (int i = threadIdx.x; i < NBINS; i += blockDim.x) {
        unsigned v = shist[i];
        if (v) atomicAdd(&g_hist[i], v);
    }
    __threadfence();
    __syncthreads();

    __shared__ int s_last;
    if (threadIdx.x == 0)
        s_last = (atomicAdd(&g_done, 1) == SCORE_GRID - 1) ? 1 : 0;
    __syncthreads();
    if (!s_last) return;
    if (threadIdx.x == 0) g_done = 0;

    const int t    = threadIdx.x;       // 256 threads, 8 bins each
    const int warp = t >> 5;
    unsigned v[8], loc = 0;
    #pragma unroll
    for (int i = 0; i < 8; i++) { v[i] = __ldcg(&g_hist[t * 8 + i]); loc += v[i]; }
    unsigned x = loc;
    #pragma unroll
    for (int off = 1; off < 32; off <<= 1) {
        unsigned y = __shfl_up_sync(0xffffffffu, x, off);
        if (lane >= off) x += y;
    }
    __shared__ unsigned ws[8];
    if (lane == 31) ws[warp] = x;
    __syncthreads();
    unsigned add = 0;
    for (int w = 0; w < warp; w++) add += ws[w];
    unsigned before = x - loc + add;
    #pragma unroll
    for (int i = 0; i < 8; i++) {
        if (before < KTARGET && before + v[i] >= KTARGET) g_cutbin = t * 8 + i;
        before += v[i];
    }
    if (t == 255 && before < KTARGET) g_cutbin = NBINS - 1;
}

// Compact candidates + lazy box decode.  (Proven, unchanged.)
__global__ void k_compact(const float* __restrict__ reg,
                          const float* __restrict__ anc,
                          const int* __restrict__ imh,
                          const int* __restrict__ imw) {
    const float H = (float)imh[0];
    const float W = (float)imw[0];
    const int cut = g_cutbin;
    const int nvec = N_ANCHORS / 4;
    int v = blockIdx.x * blockDim.x + threadIdx.x;
    const int stride = gridDim.x * blockDim.x;
    for (; v < nvec; v += stride) {
        float4 s4 = ((const float4*)g_scores)[v];
        float ss[4] = {s4.x, s4.y, s4.z, s4.w};
        #pragma unroll
        for (int q = 0; q < 4; q++) {
            float s = ss[q];
            if (s > SCORE_THR && score_bin(s) <= cut) {
                int i = v * 4 + q;
                int slot = atomicAdd(&g_cand_cnt, 1);
                if (slot < MCAP) {
                    g_cand[slot] = ((unsigned long long)__float_as_uint(s) << 32)
                                 | (unsigned long long)(0xFFFFFFFFu - (unsigned)i);
                    float4 r  = ((const float4*)reg)[i];
                    float4 an = ((const float4*)anc)[i];
                    float wa  = an.z - an.x;
                    float ha  = an.w - an.y;
                    float cxa = an.x + 0.5f * wa;
                    float cya = an.y + 0.5f * ha;
                    float cx  = cxa + r.x * 0.1f * wa;
                    float cy  = cya + r.y * 0.1f * ha;
                    float w   = expf(r.z * 0.2f) * wa;
                    float h   = expf(r.w * 0.2f) * ha;
                    float4 b;
                    b.x = fmaxf(cx - 0.5f * w, 0.0f);
                    b.y = fmaxf(cy - 0.5f * h, 0.0f);
                    b.z = fminf(cx + 0.5f * w, W);
                    b.w = fminf(cy + 0.5f * h, H);
                    g_cbox[slot] = b;
                }
            }
        }
    }
}

// Pairwise suppression bitmask: warp per row, lanes sweep columns.
// (Proven, unchanged.)
__global__ void k_masks() {
    int M = g_cand_cnt; if (M > MCAP) M = MCAP;
    const int lane = threadIdx.x & 31;
    const int gw   = blockIdx.x * (blockDim.x >> 5) + (threadIdx.x >> 5);
    const int nw   = gridDim.x * (blockDim.x >> 5);
    for (int r = gw; r < M; r += nw) {
        float4 bi = g_cbox[r];
        float ai = (bi.z - bi.x) * (bi.w - bi.y);
        #pragma unroll 4
        for (int w = 0; w < MASK_W; w++) {
            int j = w * 32 + lane;
            float4 bj = g_cbox[j];
            float xx1 = fmaxf(bi.x, bj.x);
            float yy1 = fmaxf(bi.y, bj.y);
            float xx2 = fminf(bi.z, bj.z);
            float yy2 = fminf(bi.w, bj.w);
            float inter = fmaxf(xx2 - xx1, 0.0f) * fmaxf(yy2 - yy1, 0.0f);
            float aj = (bj.z - bj.x) * (bj.w - bj.y);
            float iou = inter / (ai + aj - inter + 1e-8f);
            unsigned bits = __ballot_sync(0xffffffffu, iou > NMS_THR);
            if (lane == 0) g_mask[r * MASK_W + w] = bits;
        }
    }
}

// Single block (512 threads): cp.async prefetch of masks+boxes overlapped
// with register bitonic sort; single-warp sweep; output; state reset.
__global__ void k_tail(float* __restrict__ out, int out_size) {
    __shared__ unsigned long long skey[MCAP];           // 4 KB
    __shared__ int                spay[MCAP];           // 2 KB
    __shared__ unsigned int       smask[MCAP * MASK_W]; // 32 KB
    __shared__ float4             sbox[MCAP];           // 8 KB
    __shared__ int s_keep[MAX_DET];
    __shared__ int s_kept;
    const int tid  = threadIdx.x;
    const int lane = tid & 31;

    int M = g_cand_cnt; if (M > MCAP) M = MCAP;

    unsigned long long key = (tid < M) ? g_cand[tid] : 0ull;
    int pay = tid;

    // async prefetch: mask rows (M*64B) + candidate boxes (M*16B);
    // overlapped with the sort below, waited before the sweep.
    {
        int chunks = M * (MASK_W * 4 / 16);             // 16B chunks of masks
        for (int t = tid; t < chunks; t += blockDim.x) {
            unsigned d = smem_u32(&smask[t * 4]);
            const void* s = (const char*)g_mask + (size_t)t * 16;
            asm volatile("cp.async.cg.shared.global [%0], [%1], 16;\n"
                         :: "r"(d), "l"(s));
        }
        for (int t = tid; t < M; t += blockDim.x) {
            unsigned d = smem_u32(&sbox[t]);
            const void* s = &g_cbox[t];
            asm volatile("cp.async.cg.shared.global [%0], [%1], 16;\n"
                         :: "r"(d), "l"(s));
        }
        asm volatile("cp.async.commit_group;\n" ::: "memory");
    }

    // bitonic sort descending; shfl phases j<32, smem phases j>=32
    for (int k = 2; k <= MCAP; k <<= 1) {
        for (int j = k >> 1; j > 0; j >>= 1) {
            bool up = ((tid & k) == 0);
            unsigned long long bk; int bp;
            bool iAmLow;
            if (j >= 32) {
                __syncthreads();
                skey[tid] = key; spay[tid] = pay;
                __syncthreads();
                int p2 = tid ^ j;
                bk = skey[p2]; bp = spay[p2];
                iAmLow = (tid & j) == 0;
            } else {
                bk = __shfl_xor_sync(0xffffffffu, key, j);
                bp = __shfl_xor_sync(0xffffffffu, pay, j);
                iAmLow = (lane & j) == 0;
            }
            bool takeMax = (up == iAmLow);
            if (bk != key && ((bk > key) == takeMax)) { key = bk; pay = bp; }
        }
    }
    __syncthreads();
    skey[tid] = key; spay[tid] = pay;

    asm volatile("cp.async.wait_group 0;\n" ::: "memory");
    __syncthreads();

    // single-warp sweep; lanes prefetch 32 payloads per chunk
    if (tid < 32) {
        unsigned remv = 0;
        int kept = 0;
        int pbase = 0;
        int myu = spay[lane];
        for (int p = 0; p < M && kept < MAX_DET; p++) {
            if (p - pbase == 32) { pbase = p; myu = spay[pbase + lane]; }
            int u = __shfl_sync(0xffffffffu, myu, p - pbase);
            unsigned w = __shfl_sync(0xffffffffu, remv, u >> 5);
            if (!((w >> (u & 31)) & 1u)) {
                if (lane == 0) s_keep[kept] = p;
                kept++;
                if (lane < MASK_W) remv |= smask[u * MASK_W + lane];
            }
        }
        if (lane == 0) s_kept = kept;
    }
    __syncthreads();

    for (int i = tid; i < out_size; i += blockDim.x) out[i] = 0.0f;
    __syncthreads();
    int kept = s_kept;
    if (tid < kept) {
        int p = s_keep[tid];
        unsigned long long k = skey[p];
        unsigned aidx = 0xFFFFFFFFu - (unsigned)(k & 0xFFFFFFFFull);
        float4 b = sbox[spay[p]];
        out[tid * 4 + 0] = b.x;
        out[tid * 4 + 1] = b.y;
        out[tid * 4 + 2] = b.z;
        out[tid * 4 + 3] = b.w;
        out[4 * MAX_DET + tid] = __uint_as_float((unsigned)(k >> 32));
        out[5 * MAX_DET + tid] = (float)g_classes[aidx];
    }

    // reset device state for the next graph replay
    for (int i = tid; i < NBINS; i += blockDim.x) g_hist[i] = 0u;
    if (tid == 0) g_cand_cnt = 0;
}

extern "C" void kernel_launch(void* const* d_in, const int* in_sizes, int n_in,
                              void* d_out, int out_size) {
    const float* reg = (const float*)d_in[0];
    const float* cls = (const float*)d_in[1];
    const float* anc = (const float*)d_in[2];
    const int*   imh = (const int*)d_in[3];
    const int*   imw = (const int*)d_in[4];
    float* out = (float*)d_out;

    k_score<<<SCORE_GRID, SCORE_BLK>>>(cls);
    k_compact<<<192, 256>>>(reg, anc, imh, imw);
    k_masks<<<56, 256>>>();
    k_tail<<<1, MCAP>>>(out, out_size);
}

// round 14
// speedup vs baseline: 1.0054x; 1.0054x over previous
#include <cuda_runtime.h>
#include <math.h>

#define N_ANCHORS 196416
#define N_CLASSES 90
#define SCORE_THR 0.05f
#define NMS_THR   0.5f
#define MAX_DET   100
#define NBINS     2048
#define KTARGET   384
#define MCAP      512
#define MASK_W    (MCAP / 32)     // 16 words per mask row

#define SCORE_GRID 1023           // 8184 warps x exactly 6 iterations of 4
#define SCORE_BLK  256

// ---- scratch (static device globals; zero-initialized at load) ----
__device__ float          g_scores[N_ANCHORS];
__device__ unsigned char  g_classes[N_ANCHORS];
__device__ unsigned int   g_hist[NBINS];
__device__ int            g_done;      // last-block ticket (self-resetting)
__device__ int            g_cutbin;
__device__ int            g_cand_cnt;  // reset by k_masks
__device__ unsigned long long g_cand[MCAP];   // (score_bits<<32)|~anchor
__device__ float4         g_cbox[MCAP];
__device__ unsigned int   g_mask[MCAP * MASK_W];

__device__ __forceinline__ int score_bin(float s) {
    float d = 1.0f - s;
    if (d < 0.0f) d = 0.0f;
    return (int)(__float_as_uint(d) >> 19);
}

// Warp handles FOUR anchors per iteration; exact 6 iterations per warp.
// Last block scans bins -> g_cutbin.
__global__ void k_score(const float* __restrict__ cls) {
    __shared__ unsigned int shist[NBINS];
    for (int i = threadIdx.x; i < NBINS; i += blockDim.x) shist[i] = 0u;
    __syncthreads();

    const int lane = threadIdx.x & 31;
    const int gw   = blockIdx.x * (SCORE_BLK >> 5) + (threadIdx.x >> 5);
    const int nw   = SCORE_GRID * (SCORE_BLK >> 5);
    const bool has3 = (lane < 26);

    for (int a = 4 * gw; a < N_ANCHORS; a += 4 * nw) {
        const float* r0 = cls + (size_t)a * N_CLASSES;
        const float* r1 = r0 + N_CLASSES;
        const float* r2 = r1 + N_CLASSES;
        const float* r3 = r2 + N_CLASSES;
        float a0 = r0[lane], a1 = r0[lane + 32], a2 = has3 ? r0[lane + 64] : -1.0f;
        float b0 = r1[lane], b1 = r1[lane + 32], b2 = has3 ? r1[lane + 64] : -1.0f;
        float c0 = r2[lane], c1 = r2[lane + 32], c2 = has3 ? r2[lane + 64] : -1.0f;
        float d0 = r3[lane], d1 = r3[lane + 32], d2 = has3 ? r3[lane + 64] : -1.0f;

        float sA = a0; int cA = lane;
        if (a1 > sA) { sA = a1; cA = lane + 32; }
        if (a2 > sA) { sA = a2; cA = lane + 64; }
        float sB = b0; int cB = lane;
        if (b1 > sB) { sB = b1; cB = lane + 32; }
        if (b2 > sB) { sB = b2; cB = lane + 64; }
        float sC = c0; int cC = lane;
        if (c1 > sC) { sC = c1; cC = lane + 32; }
        if (c2 > sC) { sC = c2; cC = lane + 64; }
        float sD = d0; int cD = lane;
        if (d1 > sD) { sD = d1; cD = lane + 32; }
        if (d2 > sD) { sD = d2; cD = lane + 64; }

        unsigned mbA = __reduce_max_sync(0xffffffffu, __float_as_uint(sA));
        unsigned mbB = __reduce_max_sync(0xffffffffu, __float_as_uint(sB));
        unsigned mbC = __reduce_max_sync(0xffffffffu, __float_as_uint(sC));
        unsigned mbD = __reduce_max_sync(0xffffffffu, __float_as_uint(sD));
        unsigned mcA = __reduce_min_sync(0xffffffffu,
                         (__float_as_uint(sA) == mbA) ? (unsigned)cA : 0xFFu);
        unsigned mcB = __reduce_min_sync(0xffffffffu,
                         (__float_as_uint(sB) == mbB) ? (unsigned)cB : 0xFFu);
        unsigned mcC = __reduce_min_sync(0xffffffffu,
                         (__float_as_uint(sC) == mbC) ? (unsigned)cC : 0xFFu);
        unsigned mcD = __reduce_min_sync(0xffffffffu,
                         (__float_as_uint(sD) == mbD) ? (unsigned)cD : 0xFFu);
        if (lane == 0) {
            float msA = __uint_as_float(mbA);
            float msB = __uint_as_float(mbB);
            float msC = __uint_as_float(mbC);
            float msD = __uint_as_float(mbD);
            g_scores[a]      = msA;  g_classes[a]     = (unsigned char)mcA;
            g_scores[a + 1]  = msB;  g_classes[a + 1] = (unsigned char)mcB;
            g_scores[a + 2]  = msC;  g_classes[a + 2] = (unsigned char)mcC;
            g_scores[a + 3]  = msD;  g_classes[a + 3] = (unsigned char)mcD;
            if (msA > SCORE_THR) atomicAdd(&shist[score_bin(msA)], 1u);
            if (msB > SCORE_THR) atomicAdd(&shist[score_bin(msB)], 1u);
            if (msC > SCORE_THR) atomicAdd(&shist[score_bin(msC)], 1u);
            if (msD > SCORE_THR) atomicAdd(&shist[score_bin(msD)], 1u);
        }
    }
    __syncthreads();
    for (int i = threadIdx.x; i < NBINS; i += blockDim.x) {
        unsigned v = shist[i];
        if (v) atomicAdd(&g_hist[i], v);
    }
    __threadfence();
    __syncthreads();

    __shared__ int s_last;
    if (threadIdx.x == 0)
        s_last = (atomicAdd(&g_done, 1) == SCORE_GRID - 1) ? 1 : 0;
    __syncthreads();
    if (!s_last) return;
    if (threadIdx.x == 0) g_done = 0;

    const int t    = threadIdx.x;       // 256 threads, 8 bins each
    const int warp = t >> 5;
    unsigned v[8], loc = 0;
    #pragma unroll
    for (int i = 0; i < 8; i++) { v[i] = __ldcg(&g_hist[t * 8 + i]); loc += v[i]; }
    unsigned x = loc;
    #pragma unroll
    for (int off = 1; off < 32; off <<= 1) {
        unsigned y = __shfl_up_sync(0xffffffffu, x, off);
        if (lane >= off) x += y;
    }
    __shared__ unsigned ws[8];
    if (lane == 31) ws[warp] = x;
    __syncthreads();
    unsigned add = 0;
    for (int w = 0; w < warp; w++) add += ws[w];
    unsigned before = x - loc + add;
    #pragma unroll
    for (int i = 0; i < 8; i++) {
        if (before < KTARGET && before + v[i] >= KTARGET) g_cutbin = t * 8 + i;
        before += v[i];
    }
    if (t == 255 && before < KTARGET) g_cutbin = NBINS - 1;
}

// Compact candidates + lazy box decode.  (Proven, unchanged.)
__global__ void k_compact(const float* __restrict__ reg,
                          const float* __restrict__ anc,
                          const int* __restrict__ imh,
                          const int* __restrict__ imw) {
    const float H = (float)imh[0];
    const float W = (float)imw[0];
    const int cut = g_cutbin;
    const int nvec = N_ANCHORS / 4;
    int v = blockIdx.x * blockDim.x + threadIdx.x;
    const int stride = gridDim.x * blockDim.x;
    for (; v < nvec; v += stride) {
        float4 s4 = ((const float4*)g_scores)[v];
        float ss[4] = {s4.x, s4.y, s4.z, s4.w};
        #pragma unroll
        for (int q = 0; q < 4; q++) {
            float s = ss[q];
            if (s > SCORE_THR && score_bin(s) <= cut) {
                int i = v * 4 + q;
                int slot = atomicAdd(&g_cand_cnt, 1);
                if (slot < MCAP) {
                    g_cand[slot] = ((unsigned long long)__float_as_uint(s) << 32)
                                 | (unsigned long long)(0xFFFFFFFFu - (unsigned)i);
                    float4 r  = ((const float4*)reg)[i];
                    float4 an = ((const float4*)anc)[i];
                    float wa  = an.z - an.x;
                    float ha  = an.w - an.y;
                    float cxa = an.x + 0.5f * wa;
                    float cya = an.y + 0.5f * ha;
                    float cx  = cxa + r.x * 0.1f * wa;
                    float cy  = cya + r.y * 0.1f * ha;
                    float w   = expf(r.z * 0.2f) * wa;
                    float h   = expf(r.w * 0.2f) * ha;
                    float4 b;
                    b.x = fmaxf(cx - 0.5f * w, 0.0f);
                    b.y = fmaxf(cy - 0.5f * h, 0.0f);
                    b.z = fminf(cx + 0.5f * w, W);
                    b.w = fminf(cy + 0.5f * h, H);
                    g_cbox[slot] = b;
                }
            }
        }
    }
}

// Pairwise suppression bitmask: warp per row; also resets g_hist for the
// next graph replay (taking that work off the serial tail block).
__global__ void k_masks() {
    int M = g_cand_cnt; if (M > MCAP) M = MCAP;
    const int lane = threadIdx.x & 31;
    const int gw   = blockIdx.x * (blockDim.x >> 5) + (threadIdx.x >> 5);
    const int nw   = gridDim.x * (blockDim.x >> 5);
    for (int r = gw; r < M; r += nw) {
        float4 bi = g_cbox[r];
        float ai = (bi.z - bi.x) * (bi.w - bi.y);
        #pragma unroll 4
        for (int w = 0; w < MASK_W; w++) {
            int j = w * 32 + lane;
            float4 bj = g_cbox[j];
            float xx1 = fmaxf(bi.x, bj.x);
            float yy1 = fmaxf(bi.y, bj.y);
            float xx2 = fminf(bi.z, bj.z);
            float yy2 = fminf(bi.w, bj.w);
            float inter = fmaxf(xx2 - xx1, 0.0f) * fmaxf(yy2 - yy1, 0.0f);
            float aj = (bj.z - bj.x) * (bj.w - bj.y);
            float iou = inter / (ai + aj - inter + 1e-8f);
            unsigned bits = __ballot_sync(0xffffffffu, iou > NMS_THR);
            if (lane == 0) g_mask[r * MASK_W + w] = bits;
        }
    }
    // distributed reset of the histogram (56 blocks x 256 threads > 2048)
    int t = blockIdx.x * blockDim.x + threadIdx.x;
    if (t < NBINS) g_hist[t] = 0u;
}

// Single block (512 threads): register bitonic sort (shfl j<32, smem j>=32),
// mask copy, single-warp sweep with chunked payload prefetch, output, reset.
__global__ void k_tail(float* __restrict__ out, int out_size) {
    __shared__ unsigned long long skey[MCAP];           // 4 KB
    __shared__ int                spay[MCAP];           // 2 KB
    __shared__ unsigned int       smask[MCAP * MASK_W]; // 32 KB
    __shared__ int s_keep[MAX_DET];
    __shared__ int s_kept;
    const int tid  = threadIdx.x;
    const int lane = tid & 31;

    int M = g_cand_cnt; if (M > MCAP) M = MCAP;

    unsigned long long key = (tid < M) ? g_cand[tid] : 0ull;
    int pay = tid;

    for (int t = tid; t < M * MASK_W; t += blockDim.x) smask[t] = g_mask[t];

    for (int k = 2; k <= MCAP; k <<= 1) {
        for (int j = k >> 1; j > 0; j >>= 1) {
            bool up = ((tid & k) == 0);
            unsigned long long bk; int bp;
            bool iAmLow;
            if (j >= 32) {
                __syncthreads();
                skey[tid] = key; spay[tid] = pay;
                __syncthreads();
                int p2 = tid ^ j;
                bk = skey[p2]; bp = spay[p2];
                iAmLow = (tid & j) == 0;
            } else {
                bk = __shfl_xor_sync(0xffffffffu, key, j);
                bp = __shfl_xor_sync(0xffffffffu, pay, j);
                iAmLow = (lane & j) == 0;
            }
            bool takeMax = (up == iAmLow);
            if (bk != key && ((bk > key) == takeMax)) { key = bk; pay = bp; }
        }
    }
    __syncthreads();
    skey[tid] = key; spay[tid] = pay;
    __syncthreads();

    // single-warp sweep; lanes prefetch 32 payloads per chunk
    if (tid < 32) {
        unsigned remv = 0;
        int kept = 0;
        int pbase = 0;
        int myu = spay[lane];
        for (int p = 0; p < M && kept < MAX_DET; p++) {
            if (p - pbase == 32) { pbase = p; myu = spay[pbase + lane]; }
            int u = __shfl_sync(0xffffffffu, myu, p - pbase);
            unsigned w = __shfl_sync(0xffffffffu, remv, u >> 5);
            if (!((w >> (u & 31)) & 1u)) {
                if (lane == 0) s_keep[kept] = p;
                kept++;
                if (lane < MASK_W) remv |= smask[u * MASK_W + lane];
            }
        }
        if (lane == 0) s_kept = kept;
    }
    __syncthreads();

    for (int i = tid; i < out_size; i += blockDim.x) out[i] = 0.0f;
    __syncthreads();
    int kept = s_kept;
    if (tid < kept) {
        int p = s_keep[tid];
        unsigned long long k = skey[p];
        unsigned aidx = 0xFFFFFFFFu - (unsigned)(k & 0xFFFFFFFFull);
        float4 b = g_cbox[spay[p]];
        out[tid * 4 + 0] = b.x;
        out[tid * 4 + 1] = b.y;
        out[tid * 4 + 2] = b.z;
        out[tid * 4 + 3] = b.w;
        out[4 * MAX_DET + tid] = __uint_as_float((unsigned)(k >> 32));
        out[5 * MAX_DET + tid] = (float)g_classes[aidx];
    }

    // reset candidate counter for the next graph replay
    if (tid == 0) g_cand_cnt = 0;
}

extern "C" void kernel_launch(void* const* d_in, const int* in_sizes, int n_in,
                              void* d_out, int out_size) {
    const float* reg = (const float*)d_in[0];
    const float* cls = (const float*)d_in[1];
    const float* anc = (const float*)d_in[2];
    const int*   imh = (const int*)d_in[3];
    const int*   imw = (const int*)d_in[4];
    float* out = (float*)d_out;

    k_score<<<SCORE_GRID, SCORE_BLK>>>(cls);
    k_compact<<<192, 256>>>(reg, anc, imh, imw);
    k_masks<<<56, 256>>>();
    k_tail<<<1, MCAP>>>(out, out_size);
}

// round 16
// speedup vs baseline: 1.1544x; 1.1483x over previous
#include <cuda_runtime.h>
#include <math.h>

#define N_ANCHORS 196416
#define N_CLASSES 90
#define SCORE_THR 0.05f
#define NMS_THR   0.5f
#define MAX_DET   100
#define NBINS     2048
#define KTARGET   192
#define MCAP      256
#define MASK_W    (MCAP / 32)     // 8 words per mask row

#define SCORE_GRID 1023           // 8184 warps x exactly 6 iterations of 4
#define SCORE_BLK  256

// ---- scratch (static device globals; zero-initialized at load) ----
__device__ float          g_scores[N_ANCHORS];
__device__ unsigned char  g_classes[N_ANCHORS];
__device__ unsigned int   g_hist[NBINS];
__device__ int            g_done;      // last-block ticket (self-resetting)
__device__ int            g_cutbin;
__device__ int            g_cand_cnt;  // reset by k_tail
__device__ unsigned long long g_cand[MCAP];   // (score_bits<<32)|~anchor
__device__ float4         g_cbox[MCAP];
__device__ unsigned int   g_mask[MCAP * MASK_W];

__device__ __forceinline__ int score_bin(float s) {
    float d = 1.0f - s;
    if (d < 0.0f) d = 0.0f;
    return (int)(__float_as_uint(d) >> 19);
}

// Warp handles FOUR anchors per iteration; exact 6 iterations per warp.
// Last block scans bins -> g_cutbin.
__global__ void k_score(const float* __restrict__ cls) {
    __shared__ unsigned int shist[NBINS];
    for (int i = threadIdx.x; i < NBINS; i += blockDim.x) shist[i] = 0u;
    __syncthreads();

    const int lane = threadIdx.x & 31;
    const int gw   = blockIdx.x * (SCORE_BLK >> 5) + (threadIdx.x >> 5);
    const int nw   = SCORE_GRID * (SCORE_BLK >> 5);
    const bool has3 = (lane < 26);

    for (int a = 4 * gw; a < N_ANCHORS; a += 4 * nw) {
        const float* r0 = cls + (size_t)a * N_CLASSES;
        const float* r1 = r0 + N_CLASSES;
        const float* r2 = r1 + N_CLASSES;
        const float* r3 = r2 + N_CLASSES;
        float a0 = r0[lane], a1 = r0[lane + 32], a2 = has3 ? r0[lane + 64] : -1.0f;
        float b0 = r1[lane], b1 = r1[lane + 32], b2 = has3 ? r1[lane + 64] : -1.0f;
        float c0 = r2[lane], c1 = r2[lane + 32], c2 = has3 ? r2[lane + 64] : -1.0f;
        float d0 = r3[lane], d1 = r3[lane + 32], d2 = has3 ? r3[lane + 64] : -1.0f;

        float sA = a0; int cA = lane;
        if (a1 > sA) { sA = a1; cA = lane + 32; }
        if (a2 > sA) { sA = a2; cA = lane + 64; }
        float sB = b0; int cB = lane;
        if (b1 > sB) { sB = b1; cB = lane + 32; }
        if (b2 > sB) { sB = b2; cB = lane + 64; }
        float sC = c0; int cC = lane;
        if (c1 > sC) { sC = c1; cC = lane + 32; }
        if (c2 > sC) { sC = c2; cC = lane + 64; }
        float sD = d0; int cD = lane;
        if (d1 > sD) { sD = d1; cD = lane + 32; }
        if (d2 > sD) { sD = d2; cD = lane + 64; }

        unsigned mbA = __reduce_max_sync(0xffffffffu, __float_as_uint(sA));
        unsigned mbB = __reduce_max_sync(0xffffffffu, __float_as_uint(sB));
        unsigned mbC = __reduce_max_sync(0xffffffffu, __float_as_uint(sC));
        unsigned mbD = __reduce_max_sync(0xffffffffu, __float_as_uint(sD));
        unsigned mcA = __reduce_min_sync(0xffffffffu,
                         (__float_as_uint(sA) == mbA) ? (unsigned)cA : 0xFFu);
        unsigned mcB = __reduce_min_sync(0xffffffffu,
                         (__float_as_uint(sB) == mbB) ? (unsigned)cB : 0xFFu);
        unsigned mcC = __reduce_min_sync(0xffffffffu,
                         (__float_as_uint(sC) == mbC) ? (unsigned)cC : 0xFFu);
        unsigned mcD = __reduce_min_sync(0xffffffffu,
                         (__float_as_uint(sD) == mbD) ? (unsigned)cD : 0xFFu);
        if (lane == 0) {
            float msA = __uint_as_float(mbA);
            float msB = __uint_as_float(mbB);
            float msC = __uint_as_float(mbC);
            float msD = __uint_as_float(mbD);
            g_scores[a]      = msA;  g_classes[a]     = (unsigned char)mcA;
            g_scores[a + 1]  = msB;  g_classes[a + 1] = (unsigned char)mcB;
            g_scores[a + 2]  = msC;  g_classes[a + 2] = (unsigned char)mcC;
            g_scores[a + 3]  = msD;  g_classes[a + 3] = (unsigned char)mcD;
            if (msA > SCORE_THR) atomicAdd(&shist[score_bin(msA)], 1u);
            if (msB > SCORE_THR) atomicAdd(&shist[score_bin(msB)], 1u);
            if (msC > SCORE_THR) atomicAdd(&shist[score_bin(msC)], 1u);
            if (msD > SCORE_THR) atomicAdd(&shist[score_bin(msD)], 1u);
        }
    }
    __syncthreads();
    for (int i = threadIdx.x; i < NBINS; i += blockDim.x) {
        unsigned v = shist[i];
        if (v) atomicAdd(&g_hist[i], v);
    }
    __threadfence();
    __syncthreads();

    __shared__ int s_last;
    if (threadIdx.x == 0)
        s_last = (atomicAdd(&g_done, 1) == SCORE_GRID - 1) ? 1 : 0;
    __syncthreads();
    if (!s_last) return;
    if (threadIdx.x == 0) g_done = 0;

    const int t    = threadIdx.x;       // 256 threads, 8 bins each
    const int warp = t >> 5;
    unsigned v[8], loc = 0;
    #pragma unroll
    for (int i = 0; i < 8; i++) { v[i] = __ldcg(&g_hist[t * 8 + i]); loc += v[i]; }
    unsigned x = loc;
    #pragma unroll
    for (int off = 1; off < 32; off <<= 1) {
        unsigned y = __shfl_up_sync(0xffffffffu, x, off);
        if (lane >= off) x += y;
    }
    __shared__ unsigned ws[8];
    if (lane == 31) ws[warp] = x;
    __syncthreads();
    unsigned add = 0;
    for (int w = 0; w < warp; w++) add += ws[w];
    unsigned before = x - loc + add;
    #pragma unroll
    for (int i = 0; i < 8; i++) {
        if (before < KTARGET && before + v[i] >= KTARGET) g_cutbin = t * 8 + i;
        before += v[i];
    }
    if (t == 255 && before < KTARGET) g_cutbin = NBINS - 1;
}

// Compact candidates + lazy box decode.  (Proven, unchanged.)
__global__ void k_compact(const float* __restrict__ reg,
                          const float* __restrict__ anc,
                          const int* __restrict__ imh,
                          const int* __restrict__ imw) {
    const float H = (float)imh[0];
    const float W = (float)imw[0];
    const int cut = g_cutbin;
    const int nvec = N_ANCHORS / 4;
    int v = blockIdx.x * blockDim.x + threadIdx.x;
    const int stride = gridDim.x * blockDim.x;
    for (; v < nvec; v += stride) {
        float4 s4 = ((const float4*)g_scores)[v];
        float ss[4] = {s4.x, s4.y, s4.z, s4.w};
        #pragma unroll
        for (int q = 0; q < 4; q++) {
            float s = ss[q];
            if (s > SCORE_THR && score_bin(s) <= cut) {
                int i = v * 4 + q;
                int slot = atomicAdd(&g_cand_cnt, 1);
                if (slot < MCAP) {
                    g_cand[slot] = ((unsigned long long)__float_as_uint(s) << 32)
                                 | (unsigned long long)(0xFFFFFFFFu - (unsigned)i);
                    float4 r  = ((const float4*)reg)[i];
                    float4 an = ((const float4*)anc)[i];
                    float wa  = an.z - an.x;
                    float ha  = an.w - an.y;
                    float cxa = an.x + 0.5f * wa;
                    float cya = an.y + 0.5f * ha;
                    float cx  = cxa + r.x * 0.1f * wa;
                    float cy  = cya + r.y * 0.1f * ha;
                    float w   = expf(r.z * 0.2f) * wa;
                    float h   = expf(r.w * 0.2f) * ha;
                    float4 b;
                    b.x = fmaxf(cx - 0.5f * w, 0.0f);
                    b.y = fmaxf(cy - 0.5f * h, 0.0f);
                    b.z = fminf(cx + 0.5f * w, W);
                    b.w = fminf(cy + 0.5f * h, H);
                    g_cbox[slot] = b;
                }
            }
        }
    }
}

// Pairwise suppression bitmask: warp per row, lanes sweep columns (grid-wide
// — this parallelism is the whole reason the tail is fast). Also resets
// g_hist for the next replay.
__global__ void k_masks() {
    int M = g_cand_cnt; if (M > MCAP) M = MCAP;
    const int lane = threadIdx.x & 31;
    const int gw   = blockIdx.x * (blockDim.x >> 5) + (threadIdx.x >> 5);
    const int nw   = gridDim.x * (blockDim.x >> 5);
    for (int r = gw; r < M; r += nw) {
        float4 bi = g_cbox[r];
        float ai = (bi.z - bi.x) * (bi.w - bi.y);
        #pragma unroll
        for (int w = 0; w < MASK_W; w++) {
            int j = w * 32 + lane;
            float4 bj = g_cbox[j];
            float xx1 = fmaxf(bi.x, bj.x);
            float yy1 = fmaxf(bi.y, bj.y);
            float xx2 = fminf(bi.z, bj.z);
            float yy2 = fminf(bi.w, bj.w);
            float inter = fmaxf(xx2 - xx1, 0.0f) * fmaxf(yy2 - yy1, 0.0f);
            float aj = (bj.z - bj.x) * (bj.w - bj.y);
            float iou = inter / (ai + aj - inter + 1e-8f);
            unsigned bits = __ballot_sync(0xffffffffu, iou > NMS_THR);
            if (lane == 0) g_mask[r * MASK_W + w] = bits;
        }
    }
    // distributed reset of the histogram
    int t = blockIdx.x * blockDim.x + threadIdx.x;
    if (t < NBINS) g_hist[t] = 0u;
}

// Single block (256 threads): register bitonic sort (shfl j<32, smem j>=32:
// 6 passes), mask copy, single-warp sweep, output, counter reset.
__global__ void k_tail(float* __restrict__ out, int out_size) {
    __shared__ unsigned long long skey[MCAP];           // 2 KB
    __shared__ int                spay[MCAP];           // 1 KB
    __shared__ unsigned int       smask[MCAP * MASK_W]; // 8 KB
    __shared__ int s_keep[MAX_DET];
    __shared__ int s_kept;
    const int tid  = threadIdx.x;
    const int lane = tid & 31;

    int M = g_cand_cnt; if (M > MCAP) M = MCAP;

    unsigned long long key = (tid < M) ? g_cand[tid] : 0ull;
    int pay = tid;

    for (int t = tid; t < M * MASK_W; t += blockDim.x) smask[t] = g_mask[t];

    for (int k = 2; k <= MCAP; k <<= 1) {
        for (int j = k >> 1; j > 0; j >>= 1) {
            bool up = ((tid & k) == 0);
            unsigned long long bk; int bp;
            bool iAmLow;
            if (j >= 32) {
                __syncthreads();
                skey[tid] = key; spay[tid] = pay;
                __syncthreads();
                int p2 = tid ^ j;
                bk = skey[p2]; bp = spay[p2];
                iAmLow = (tid & j) == 0;
            } else {
                bk = __shfl_xor_sync(0xffffffffu, key, j);
                bp = __shfl_xor_sync(0xffffffffu, pay, j);
                iAmLow = (lane & j) == 0;
            }
            bool takeMax = (up == iAmLow);
            if (bk != key && ((bk > key) == takeMax)) { key = bk; pay = bp; }
        }
    }
    __syncthreads();
    skey[tid] = key; spay[tid] = pay;
    __syncthreads();

    // single-warp sweep; lanes prefetch 32 payloads per chunk;
    // remv bitset (256 bits) lives in lanes 0..7
    if (tid < 32) {
        unsigned remv = 0;
        int kept = 0;
        int pbase = 0;
        int myu = spay[lane];
        for (int p = 0; p < M && kept < MAX_DET; p++) {
            if (p - pbase == 32) { pbase = p; myu = spay[pbase + lane]; }
            int u = __shfl_sync(0xffffffffu, myu, p - pbase);
            unsigned w = __shfl_sync(0xffffffffu, remv, u >> 5);
            if (!((w >> (u & 31)) & 1u)) {
                if (lane == 0) s_keep[kept] = p;
                kept++;
                if (lane < MASK_W) remv |= smask[u * MASK_W + lane];
            }
        }
        if (lane == 0) s_kept = kept;
    }
    __syncthreads();

    for (int i = tid; i < out_size; i += blockDim.x) out[i] = 0.0f;
    __syncthreads();
    int kept = s_kept;
    if (tid < kept) {
        int p = s_keep[tid];
        unsigned long long k = skey[p];
        unsigned aidx = 0xFFFFFFFFu - (unsigned)(k & 0xFFFFFFFFull);
        float4 b = g_cbox[spay[p]];
        out[tid * 4 + 0] = b.x;
        out[tid * 4 + 1] = b.y;
        out[tid * 4 + 2] = b.z;
        out[tid * 4 + 3] = b.w;
        out[4 * MAX_DET + tid] = __uint_as_float((unsigned)(k >> 32));
        out[5 * MAX_DET + tid] = (float)g_classes[aidx];
    }

    // reset candidate counter for the next graph replay
    if (tid == 0) g_cand_cnt = 0;
}

extern "C" void kernel_launch(void* const* d_in, const int* in_sizes, int n_in,
                              void* d_out, int out_size) {
    const float* reg = (const float*)d_in[0];
    const float* cls = (const float*)d_in[1];
    const float* anc = (const float*)d_in[2];
    const int*   imh = (const int*)d_in[3];
    const int*   imw = (const int*)d_in[4];
    float* out = (float*)d_out;

    k_score<<<SCORE_GRID, SCORE_BLK>>>(cls);
    k_compact<<<192, 256>>>(reg, anc, imh, imw);
    k_masks<<<56, 256>>>();
    k_tail<<<1, MCAP>>>(out, out_size);
}